// round 9
// baseline (speedup 1.0000x reference)
#include <cuda_runtime.h>
#include <cuda_fp16.h>
#include <math.h>

#define NN 100000
#define EE 3200000
#define IN_DIM 128
#define HD 16
#define H2 32
#define OUT_DIM 32
#define MSG_EPS 1e-7f
#define BN_EPS 1e-5f
#define SB 128                      // stats blocks
#define RPB ((NN + SB - 1) / SB)    // rows per stats block
#define NSCAN ((NN + 1023) / 1024)  // scan blocks (98)

// ---------------- device scratch (EXACT R8 layout: names, sizes, order — DO NOT TOUCH) --
static __device__ int   g_is64;
static __device__ int   g_deg[NN];
static __device__ int   g_ptr[NN + 1];
static __device__ int   g_cur[NN];
static __device__ int   g_csr[EE];
static __device__ int   g_maskpos[NN];
static __device__ int   g_bsum[NSCAN + 32];
static __device__ int   g_bsum2[NSCAN + 32];
static __device__ float g_xp[NN * HD];        // conv1 projected x (residual)
static __device__ float g_PQ[NN * 2 * HD];    // first NN*16 words: packed half2(P,Q) per channel
static __device__ float g_t[NN * H2];         // post-W1 pre-BN activations
static __device__ float g_h[NN * HD];         // layer output (after relu)
static __device__ float g_psum[SB * H2];
static __device__ float g_psq[SB * H2];

// pack/unpack helpers (register-only bit casts; memory ops stay scalar 32-bit)
__device__ __forceinline__ unsigned int pq_pack(float p, float q) {
    __half2 h = __floats2half2_rn(p, q);
    return *reinterpret_cast<unsigned int*>(&h);
}
__device__ __forceinline__ float2 pq_unpack(unsigned int u) {
    __half2 h = *reinterpret_cast<__half2*>(&u);
    return __half22float2(h);
}

// ---------------- zero degree + dtype detect ----------------
__global__ void k_zero_detect(const unsigned int* __restrict__ w) {
    int i = blockIdx.x * blockDim.x + threadIdx.x;
    if (i < NN) g_deg[i] = 0;
    if (blockIdx.x == 0 && threadIdx.x == 0) {
        int z = 1;
        for (int k = 1; k < 64; k += 2)
            if (w[k] != 0u) { z = 0; break; }
        g_is64 = z;
    }
}

// degree histogram straight from edge_index (dst half only)
__global__ void k_hist(const int* __restrict__ ei) {
    int e = blockIdx.x * blockDim.x + threadIdx.x;
    if (e >= EE) return;
    int d = g_is64 ? ei[2 * (EE + e)] : ei[EE + e];
    atomicAdd(&g_deg[d], 1);
}

// ---------------- 3-kernel exclusive scan over (deg, mask) simultaneously ----------
__device__ __forceinline__ int warp_incl_scan(int x, int lane) {
#pragma unroll
    for (int o = 1; o < 32; o <<= 1) {
        int y = __shfl_up_sync(0xffffffffu, x, o);
        if (lane >= o) x += y;
    }
    return x;
}

__global__ void kScanA(const int* __restrict__ mask) {
    __shared__ int sh[64];
    int tid = threadIdx.x;
    int i = blockIdx.x * 1024 + tid;
    int v0 = 0, v1 = 0;
    if (i < NN) { v0 = g_deg[i]; v1 = (mask[i] != 0); }
    int x0 = v0, x1 = v1;
#pragma unroll
    for (int o = 16; o; o >>= 1) {
        x0 += __shfl_down_sync(0xffffffffu, x0, o);
        x1 += __shfl_down_sync(0xffffffffu, x1, o);
    }
    if ((tid & 31) == 0) { sh[tid >> 5] = x0; sh[32 + (tid >> 5)] = x1; }
    __syncthreads();
    if (tid < 32) {
        int y0 = sh[tid], y1 = sh[32 + tid];
#pragma unroll
        for (int o = 16; o; o >>= 1) {
            y0 += __shfl_down_sync(0xffffffffu, y0, o);
            y1 += __shfl_down_sync(0xffffffffu, y1, o);
        }
        if (tid == 0) { g_bsum[blockIdx.x] = y0; g_bsum2[blockIdx.x] = y1; }
    }
}

__global__ void kScanB() {
    __shared__ int wsum[8];
    int tid = threadIdx.x;  // 128 threads
    int lane = tid & 31, wrp = tid >> 5;
    int v0 = (tid < NSCAN) ? g_bsum[tid] : 0;
    int v1 = (tid < NSCAN) ? g_bsum2[tid] : 0;
    int x0 = warp_incl_scan(v0, lane);
    int x1 = warp_incl_scan(v1, lane);
    if (lane == 31) { wsum[wrp] = x0; wsum[4 + wrp] = x1; }
    __syncthreads();
    int off0 = 0, off1 = 0;
    for (int w = 0; w < wrp; w++) { off0 += wsum[w]; off1 += wsum[4 + w]; }
    if (tid < NSCAN) {
        g_bsum[tid] = x0 - v0 + off0;
        g_bsum2[tid] = x1 - v1 + off1;
    }
}

__global__ void kScanC(const int* __restrict__ mask) {
    __shared__ int wsum[64];
    int tid = threadIdx.x;
    int b = blockIdx.x;
    int i = b * 1024 + tid;
    int v0 = 0, v1 = 0;
    if (i < NN) { v0 = g_deg[i]; v1 = (mask[i] != 0); }
    int lane = tid & 31, wrp = tid >> 5;
    int x0 = warp_incl_scan(v0, lane);
    int x1 = warp_incl_scan(v1, lane);
    if (lane == 31) { wsum[wrp] = x0; wsum[32 + wrp] = x1; }
    __syncthreads();
    if (tid < 32) {
        wsum[tid] = warp_incl_scan(wsum[tid], tid & 31);
        wsum[32 + tid] = warp_incl_scan(wsum[32 + tid], tid & 31);
    }
    __syncthreads();
    int e0 = x0 - v0 + ((wrp > 0) ? wsum[wrp - 1] : 0) + g_bsum[b];
    int e1 = x1 - v1 + ((wrp > 0) ? wsum[32 + wrp - 1] : 0) + g_bsum2[b];
    if (i < NN) {
        g_ptr[i] = e0; g_cur[i] = e0;
        g_maskpos[i] = e1;
    }
    if (b == 0 && tid == 0) g_ptr[NN] = EE;
}

// scatter src into dst-sorted buckets, reading edge_index directly
__global__ void k_scatter(const int* __restrict__ ei) {
    int e = blockIdx.x * blockDim.x + threadIdx.x;
    if (e >= EE) return;
    int s, d;
    if (g_is64) { s = ei[2 * e]; d = ei[2 * (EE + e)]; }
    else        { s = ei[e];     d = ei[EE + e]; }
    int p = atomicAdd(&g_cur[d], 1);
    g_csr[p] = s;
}

// ---------------- conv1 node pre-pass (smem-tiled GEMM, coalesced x loads) ---------
__global__ void k_pre1(const float* __restrict__ x, const float* __restrict__ W,
                       const float* __restrict__ bsrc) {
    __shared__ float ws[IN_DIM * HD];
    __shared__ float xs[256 * 33];
    __shared__ float bs[HD];
    int tid = threadIdx.x;
    for (int i = tid; i < IN_DIM * HD; i += 256) ws[i] = W[i];
    if (tid < HD) bs[tid] = bsrc[tid];
    int n0 = blockIdx.x * 256;
    int n = n0 + tid;
    int lane = tid & 31, wrp = tid >> 5;
    float acc[HD];
#pragma unroll
    for (int c = 0; c < HD; c++) acc[c] = 0.f;
#pragma unroll
    for (int kc = 0; kc < 4; kc++) {
        __syncthreads();
        for (int r = wrp; r < 256; r += 8) {
            int row = n0 + r; if (row >= NN) row = NN - 1;
            xs[r * 33 + lane] = __ldg(x + (size_t)row * IN_DIM + kc * 32 + lane);
        }
        __syncthreads();
#pragma unroll
        for (int j = 0; j < 32; j++) {
            float xv = xs[tid * 33 + j];
            const float4* wr = (const float4*)&ws[(kc * 32 + j) * HD];
            float4 w0 = wr[0], w1 = wr[1], w2 = wr[2], w3 = wr[3];
            acc[0]  = fmaf(xv, w0.x, acc[0]);  acc[1]  = fmaf(xv, w0.y, acc[1]);
            acc[2]  = fmaf(xv, w0.z, acc[2]);  acc[3]  = fmaf(xv, w0.w, acc[3]);
            acc[4]  = fmaf(xv, w1.x, acc[4]);  acc[5]  = fmaf(xv, w1.y, acc[5]);
            acc[6]  = fmaf(xv, w1.z, acc[6]);  acc[7]  = fmaf(xv, w1.w, acc[7]);
            acc[8]  = fmaf(xv, w2.x, acc[8]);  acc[9]  = fmaf(xv, w2.y, acc[9]);
            acc[10] = fmaf(xv, w2.z, acc[10]); acc[11] = fmaf(xv, w2.w, acc[11]);
            acc[12] = fmaf(xv, w3.x, acc[12]); acc[13] = fmaf(xv, w3.y, acc[13]);
            acc[14] = fmaf(xv, w3.z, acc[14]); acc[15] = fmaf(xv, w3.w, acc[15]);
        }
    }
    if (n >= NN) return;
    float xp[HD];
#pragma unroll
    for (int c = 0; c < HD; c++) xp[c] = acc[c] + bs[c];
    float4* xpo = (float4*)(g_xp + (size_t)n * HD);
#pragma unroll
    for (int q = 0; q < 4; q++)
        xpo[q] = make_float4(xp[q*4], xp[q*4+1], xp[q*4+2], xp[q*4+3]);
    unsigned int* pqo = (unsigned int*)g_PQ + (size_t)n * HD;   // scalar 4B stores only
#pragma unroll
    for (int c = 0; c < HD; c++) {
        float m = fmaxf(xp[c], 0.f) + MSG_EPS;
        float p = __expf(m);
        pqo[c] = pq_pack(p, p * m);
    }
}

// ---------------- aggregation + residual + W1: warp per node, paired edges ----------
// lanes 0-15 = even edge (channel = lane), lanes 16-31 = odd edge (channel = lane-16)
__global__ void k_aggr(int conv, const float* __restrict__ W1, const float* __restrict__ b1) {
    __shared__ float w1s[HD * H2];
    __shared__ float b1s[H2];
    for (int i = threadIdx.x; i < HD * H2; i += blockDim.x) w1s[i] = W1[i];
    if (threadIdx.x < H2) b1s[threadIdx.x] = b1[threadIdx.x];
    __syncthreads();
    int n = (blockIdx.x * blockDim.x + threadIdx.x) >> 5;
    int lane = threadIdx.x & 31;
    if (n >= NN) return;
    int hw = lane >> 4;      // which edge of the pair
    int cl = lane & 15;      // channel
    int s = g_ptr[n], e = g_ptr[n + 1];
    const unsigned int* __restrict__ PQ = (const unsigned int*)g_PQ;
    float ax = 0.f, ay = 0.f;
    int p = s;
    // 8 edges (4 pairs) per iteration
    for (; p + 8 <= e; p += 8) {
        int i0 = __ldg(g_csr + p     + hw);
        int i1 = __ldg(g_csr + p + 2 + hw);
        int i2 = __ldg(g_csr + p + 4 + hw);
        int i3 = __ldg(g_csr + p + 6 + hw);
        float2 f0 = pq_unpack(__ldg(PQ + (size_t)i0 * HD + cl));
        float2 f1 = pq_unpack(__ldg(PQ + (size_t)i1 * HD + cl));
        float2 f2 = pq_unpack(__ldg(PQ + (size_t)i2 * HD + cl));
        float2 f3 = pq_unpack(__ldg(PQ + (size_t)i3 * HD + cl));
        ax += (f0.x + f1.x) + (f2.x + f3.x);
        ay += (f0.y + f1.y) + (f2.y + f3.y);
    }
    for (; p < e; p += 2) {
        int q = p + hw;
        int idx = __ldg(g_csr + (q < e ? q : p));
        float2 v = pq_unpack(__ldg(PQ + (size_t)idx * HD + cl));
        if (q < e) { ax += v.x; ay += v.y; }
    }
    // combine the two half-warps; lane c (<16) then holds channel c sums directly
    ax += __shfl_xor_sync(0xffffffffu, ax, 16);
    ay += __shfl_xor_sync(0xffffffffu, ay, 16);
    float h1 = 0.f;
    if (lane < HD) {
        float aggr = (e > s) ? (ay / ax) : 0.f;
        const float* resid = (conv == 1) ? g_xp : g_h;
        h1 = aggr + resid[(size_t)n * HD + lane];
    }
    float tv = b1s[lane];
#pragma unroll
    for (int cc = 0; cc < HD; cc++) {
        float hc = __shfl_sync(0xffffffffu, h1, cc);
        tv = fmaf(hc, w1s[cc * H2 + lane], tv);
    }
    g_t[(size_t)n * H2 + lane] = tv;
}

// ---------------- deterministic BN stats (partials) ----------------
__global__ void k_stats1() {
    __shared__ float sh[256];
    int b = blockIdx.x, tid = threadIdx.x;
    int c = tid & 31, rr = tid >> 5;
    float s = 0.f, q = 0.f;
    int r0 = b * RPB;
    int r1 = min(NN, (b + 1) * RPB);
    for (int r = r0 + rr; r < r1; r += 8) {
        float v = g_t[(size_t)r * H2 + c];
        s += v;
        q = fmaf(v, v, q);
    }
    sh[tid] = s;
    __syncthreads();
    if (tid < 32) {
        float t2 = 0.f;
#pragma unroll
        for (int k = 0; k < 8; k++) t2 += sh[tid + 32 * k];
        g_psum[b * 32 + tid] = t2;
    }
    __syncthreads();
    sh[tid] = q;
    __syncthreads();
    if (tid < 32) {
        float t2 = 0.f;
#pragma unroll
        for (int k = 0; k < 8; k++) t2 += sh[tid + 32 * k];
        g_psq[b * 32 + tid] = t2;
    }
}

// per-block redundant final stats reduction -> smem mu/rsig (scalar only, double accum)
__device__ __forceinline__ void stats_prologue(float* smu, float* srs, int tid) {
    if (tid < 32) {
        double s = 0.0, q = 0.0;
        for (int b = 0; b < SB; b++) {
            s += (double)g_psum[b * 32 + tid];
            q += (double)g_psq[b * 32 + tid];
        }
        double mu = s / (double)NN;
        double var = q / (double)NN - mu * mu;
        smu[tid] = (float)mu;
        srs[tid] = (float)rsqrt(var + (double)BN_EPS);
    }
    __syncthreads();
}

// ---------------- conv1 tail fused with conv2 pre: BN->relu->W2->relu => g_h, g_PQ ----
__global__ void k_post1(const float* __restrict__ gam, const float* __restrict__ bet,
                        const float* __restrict__ W2, const float* __restrict__ b2) {
    __shared__ float w2s[H2 * HD];
    __shared__ float sc[H2], sb[H2], smu[H2], srs[H2], b2s[HD];
    int tid = threadIdx.x;
    stats_prologue(smu, srs, tid);
    for (int i = tid; i < H2 * HD; i += blockDim.x) w2s[i] = W2[i];
    if (tid < H2) { sc[tid] = gam[tid]; sb[tid] = bet[tid]; }
    if (tid < HD) b2s[tid] = b2[tid];
    __syncthreads();
    int n = blockIdx.x * blockDim.x + tid;
    if (n >= NN) return;
    float r[H2];
    const float4* t4 = (const float4*)(g_t + (size_t)n * H2);
#pragma unroll
    for (int q = 0; q < H2 / 4; q++) {
        float4 v = t4[q];
        const float* f = (const float*)&v;
#pragma unroll
        for (int kk = 0; kk < 4; kk++) {
            int j = q * 4 + kk;
            float u = (f[kk] - smu[j]) * srs[j] * sc[j] + sb[j];
            r[j] = fmaxf(u, 0.f);
        }
    }
    float o[HD];
#pragma unroll
    for (int c = 0; c < HD; c++) o[c] = b2s[c];
#pragma unroll
    for (int j = 0; j < H2; j++) {
        float rj = r[j];
#pragma unroll
        for (int c = 0; c < HD; c++) o[c] = fmaf(rj, w2s[j * HD + c], o[c]);
    }
    float hv[HD];
#pragma unroll
    for (int c = 0; c < HD; c++) hv[c] = fmaxf(o[c], 0.f);
    float4* ho = (float4*)(g_h + (size_t)n * HD);
#pragma unroll
    for (int q = 0; q < 4; q++)
        ho[q] = make_float4(hv[q*4], hv[q*4+1], hv[q*4+2], hv[q*4+3]);
    unsigned int* pqo = (unsigned int*)g_PQ + (size_t)n * HD;   // scalar 4B stores only
#pragma unroll
    for (int c = 0; c < HD; c++) {
        float m = hv[c] + MSG_EPS;
        float p = __expf(m);
        pqo[c] = pq_pack(p, p * m);
    }
}

// ---------------- conv2 tail + fc + masked compaction (direct write to out) ----------
__global__ void k_post2(const float* __restrict__ gam, const float* __restrict__ bet,
                        const float* __restrict__ W2, const float* __restrict__ b2,
                        const float* __restrict__ fcW, const float* __restrict__ fcb,
                        const int* __restrict__ mask, float* __restrict__ out) {
    __shared__ float w2s[H2 * HD];
    __shared__ float fws[HD * OUT_DIM];
    __shared__ float sc[H2], sb[H2], smu[H2], srs[H2], b2s[HD], fbs[OUT_DIM];
    int tid = threadIdx.x;
    stats_prologue(smu, srs, tid);
    for (int i = tid; i < H2 * HD; i += blockDim.x) w2s[i] = W2[i];
    for (int i = tid; i < HD * OUT_DIM; i += blockDim.x) fws[i] = fcW[i];
    if (tid < H2) { sc[tid] = gam[tid]; sb[tid] = bet[tid]; fbs[tid] = fcb[tid]; }
    if (tid < HD) b2s[tid] = b2[tid];
    __syncthreads();
    int n = blockIdx.x * blockDim.x + tid;
    if (n >= NN) return;
    float r[H2];
    const float4* t4 = (const float4*)(g_t + (size_t)n * H2);
#pragma unroll
    for (int q = 0; q < H2 / 4; q++) {
        float4 v = t4[q];
        const float* f = (const float*)&v;
#pragma unroll
        for (int kk = 0; kk < 4; kk++) {
            int j = q * 4 + kk;
            float u = (f[kk] - smu[j]) * srs[j] * sc[j] + sb[j];
            r[j] = fmaxf(u, 0.f);
        }
    }
    float hr[HD];
#pragma unroll
    for (int c = 0; c < HD; c++) hr[c] = b2s[c];
#pragma unroll
    for (int j = 0; j < H2; j++) {
        float rj = r[j];
#pragma unroll
        for (int c = 0; c < HD; c++) hr[c] = fmaf(rj, w2s[j * HD + c], hr[c]);
    }
#pragma unroll
    for (int c = 0; c < HD; c++) hr[c] = fmaxf(hr[c], 0.f);
    if (mask[n] == 0) return;
    float ov[OUT_DIM];
#pragma unroll
    for (int c2 = 0; c2 < OUT_DIM; c2++) ov[c2] = fbs[c2];
#pragma unroll
    for (int c = 0; c < HD; c++) {
        float hc = hr[c];
#pragma unroll
        for (int c2 = 0; c2 < OUT_DIM; c2++) ov[c2] = fmaf(hc, fws[c * OUT_DIM + c2], ov[c2]);
    }
    int pos = g_maskpos[n];
    float4* od = (float4*)(out + (size_t)pos * OUT_DIM);
#pragma unroll
    for (int q = 0; q < OUT_DIM / 4; q++)
        od[q] = make_float4(ov[q*4], ov[q*4+1], ov[q*4+2], ov[q*4+3]);
}

// ---------------- host ----------------
extern "C" void kernel_launch(void* const* d_in, const int* in_sizes, int n_in,
                              void* d_out, int out_size) {
    int base = (in_sizes[0] == 2 * EE) ? 0 : 1;
    const int*   edge_index = (const int*)d_in[base + 0];
    const float* x          = (const float*)d_in[base + 2];
    const int*   node_mask  = (const int*)d_in[base + 3];
    const float* W_src = (const float*)d_in[base + 4];
    const float* b_src = (const float*)d_in[base + 5];
    const float* c1_W1 = (const float*)d_in[base + 6];
    const float* c1_b1 = (const float*)d_in[base + 7];
    const float* c1_g  = (const float*)d_in[base + 8];
    const float* c1_be = (const float*)d_in[base + 9];
    const float* c1_W2 = (const float*)d_in[base + 10];
    const float* c1_b2 = (const float*)d_in[base + 11];
    const float* c2_W1 = (const float*)d_in[base + 12];
    const float* c2_b1 = (const float*)d_in[base + 13];
    const float* c2_g  = (const float*)d_in[base + 14];
    const float* c2_be = (const float*)d_in[base + 15];
    const float* c2_W2 = (const float*)d_in[base + 16];
    const float* c2_b2 = (const float*)d_in[base + 17];
    const float* fc_W  = (const float*)d_in[base + 18];
    const float* fc_b  = (const float*)d_in[base + 19];
    float* out = (float*)d_out;

    const int TPB = 256;
    const int EB = (EE + TPB - 1) / TPB;       // 12500
    const int NB = (NN + TPB - 1) / TPB;       // 391
    const int WB = (NN * 32 + TPB - 1) / TPB;  // 12500 (warp-per-node)

    // CSR build + mask positions
    k_zero_detect<<<NB, TPB>>>((const unsigned int*)edge_index);
    k_hist<<<EB, TPB>>>(edge_index);
    kScanA<<<NSCAN, 1024>>>(node_mask);
    kScanB<<<1, 128>>>();
    kScanC<<<NSCAN, 1024>>>(node_mask);
    k_scatter<<<EB, TPB>>>(edge_index);

    // conv1
    k_pre1<<<NB, TPB>>>(x, W_src, b_src);
    k_aggr<<<WB, TPB>>>(1, c1_W1, c1_b1);
    k_stats1<<<SB, 256>>>();
    k_post1<<<NB, TPB>>>(c1_g, c1_be, c1_W2, c1_b2);

    // conv2 + fc + masked write
    k_aggr<<<WB, TPB>>>(2, c2_W1, c2_b1);
    k_stats1<<<SB, 256>>>();
    k_post2<<<NB, TPB>>>(c2_g, c2_be, c2_W2, c2_b2, fc_W, fc_b, node_mask, out);
}

// round 10
// speedup vs baseline: 1.0405x; 1.0405x over previous
#include <cuda_runtime.h>
#include <math.h>

#define NN 100000
#define EE 3200000
#define IN_DIM 128
#define HD 16
#define H2 32
#define OUT_DIM 32
#define MSG_EPS 1e-7f
#define BN_EPS 1e-5f
#define SB 128                      // stats blocks
#define RPB ((NN + SB - 1) / SB)    // rows per stats block
#define NSCAN ((NN + 1023) / 1024)  // scan blocks (98)

// ---------------- device scratch (EXACT R8 layout: names, sizes, order — DO NOT TOUCH) --
static __device__ int   g_is64;
static __device__ int   g_deg[NN];
static __device__ int   g_ptr[NN + 1];
static __device__ int   g_cur[NN];
static __device__ int   g_csr[EE];
static __device__ int   g_maskpos[NN];
static __device__ int   g_bsum[NSCAN + 32];
static __device__ int   g_bsum2[NSCAN + 32];
static __device__ float g_xp[NN * HD];        // conv1 projected x (residual)
static __device__ float g_PQ[NN * 2 * HD];    // per-node [P(16) | Q(16)]
static __device__ float g_t[NN * H2];         // post-W1 pre-BN activations
static __device__ float g_h[NN * HD];         // layer output (after relu)
static __device__ float g_psum[SB * H2];
static __device__ float g_psq[SB * H2];

// ---------------- zero degree + dtype detect ----------------
__global__ void k_zero_detect(const unsigned int* __restrict__ w) {
    int i = blockIdx.x * blockDim.x + threadIdx.x;
    if (i < NN) g_deg[i] = 0;
    if (blockIdx.x == 0 && threadIdx.x == 0) {
        int z = 1;
        for (int k = 1; k < 64; k += 2)
            if (w[k] != 0u) { z = 0; break; }
        g_is64 = z;
    }
}

// degree histogram straight from edge_index (dst half only)
__global__ void k_hist(const int* __restrict__ ei) {
    int e = blockIdx.x * blockDim.x + threadIdx.x;
    if (e >= EE) return;
    int d = g_is64 ? ei[2 * (EE + e)] : ei[EE + e];
    atomicAdd(&g_deg[d], 1);
}

// ---------------- 3-kernel exclusive scan over (deg, mask) simultaneously ----------
__device__ __forceinline__ int warp_incl_scan(int x, int lane) {
#pragma unroll
    for (int o = 1; o < 32; o <<= 1) {
        int y = __shfl_up_sync(0xffffffffu, x, o);
        if (lane >= o) x += y;
    }
    return x;
}

__global__ void kScanA(const int* __restrict__ mask) {
    __shared__ int sh[64];
    int tid = threadIdx.x;
    int i = blockIdx.x * 1024 + tid;
    int v0 = 0, v1 = 0;
    if (i < NN) { v0 = g_deg[i]; v1 = (mask[i] != 0); }
    int x0 = v0, x1 = v1;
#pragma unroll
    for (int o = 16; o; o >>= 1) {
        x0 += __shfl_down_sync(0xffffffffu, x0, o);
        x1 += __shfl_down_sync(0xffffffffu, x1, o);
    }
    if ((tid & 31) == 0) { sh[tid >> 5] = x0; sh[32 + (tid >> 5)] = x1; }
    __syncthreads();
    if (tid < 32) {
        int y0 = sh[tid], y1 = sh[32 + tid];
#pragma unroll
        for (int o = 16; o; o >>= 1) {
            y0 += __shfl_down_sync(0xffffffffu, y0, o);
            y1 += __shfl_down_sync(0xffffffffu, y1, o);
        }
        if (tid == 0) { g_bsum[blockIdx.x] = y0; g_bsum2[blockIdx.x] = y1; }
    }
}

__global__ void kScanB() {
    __shared__ int wsum[8];
    int tid = threadIdx.x;  // 128 threads
    int lane = tid & 31, wrp = tid >> 5;
    int v0 = (tid < NSCAN) ? g_bsum[tid] : 0;
    int v1 = (tid < NSCAN) ? g_bsum2[tid] : 0;
    int x0 = warp_incl_scan(v0, lane);
    int x1 = warp_incl_scan(v1, lane);
    if (lane == 31) { wsum[wrp] = x0; wsum[4 + wrp] = x1; }
    __syncthreads();
    int off0 = 0, off1 = 0;
    for (int w = 0; w < wrp; w++) { off0 += wsum[w]; off1 += wsum[4 + w]; }
    if (tid < NSCAN) {
        g_bsum[tid] = x0 - v0 + off0;
        g_bsum2[tid] = x1 - v1 + off1;
    }
}

__global__ void kScanC(const int* __restrict__ mask) {
    __shared__ int wsum[64];
    int tid = threadIdx.x;
    int b = blockIdx.x;
    int i = b * 1024 + tid;
    int v0 = 0, v1 = 0;
    if (i < NN) { v0 = g_deg[i]; v1 = (mask[i] != 0); }
    int lane = tid & 31, wrp = tid >> 5;
    int x0 = warp_incl_scan(v0, lane);
    int x1 = warp_incl_scan(v1, lane);
    if (lane == 31) { wsum[wrp] = x0; wsum[32 + wrp] = x1; }
    __syncthreads();
    if (tid < 32) {
        wsum[tid] = warp_incl_scan(wsum[tid], tid & 31);
        wsum[32 + tid] = warp_incl_scan(wsum[32 + tid], tid & 31);
    }
    __syncthreads();
    int e0 = x0 - v0 + ((wrp > 0) ? wsum[wrp - 1] : 0) + g_bsum[b];
    int e1 = x1 - v1 + ((wrp > 0) ? wsum[32 + wrp - 1] : 0) + g_bsum2[b];
    if (i < NN) {
        g_ptr[i] = e0; g_cur[i] = e0;
        g_maskpos[i] = e1;
    }
    if (b == 0 && tid == 0) g_ptr[NN] = EE;
}

// scatter src into dst-sorted buckets, reading edge_index directly
__global__ void k_scatter(const int* __restrict__ ei) {
    int e = blockIdx.x * blockDim.x + threadIdx.x;
    if (e >= EE) return;
    int s, d;
    if (g_is64) { s = ei[2 * e]; d = ei[2 * (EE + e)]; }
    else        { s = ei[e];     d = ei[EE + e]; }
    int p = atomicAdd(&g_cur[d], 1);
    g_csr[p] = s;
}

// ---------------- conv1 node pre-pass (smem-tiled GEMM, coalesced x loads) ---------
__global__ void k_pre1(const float* __restrict__ x, const float* __restrict__ W,
                       const float* __restrict__ bsrc) {
    __shared__ float ws[IN_DIM * HD];
    __shared__ float xs[256 * 33];
    __shared__ float bs[HD];
    int tid = threadIdx.x;
    for (int i = tid; i < IN_DIM * HD; i += 256) ws[i] = W[i];
    if (tid < HD) bs[tid] = bsrc[tid];
    int n0 = blockIdx.x * 256;
    int n = n0 + tid;
    int lane = tid & 31, wrp = tid >> 5;
    float acc[HD];
#pragma unroll
    for (int c = 0; c < HD; c++) acc[c] = 0.f;
#pragma unroll
    for (int kc = 0; kc < 4; kc++) {
        __syncthreads();
        for (int r = wrp; r < 256; r += 8) {
            int row = n0 + r; if (row >= NN) row = NN - 1;
            xs[r * 33 + lane] = __ldg(x + (size_t)row * IN_DIM + kc * 32 + lane);
        }
        __syncthreads();
#pragma unroll
        for (int j = 0; j < 32; j++) {
            float xv = xs[tid * 33 + j];
            const float4* wr = (const float4*)&ws[(kc * 32 + j) * HD];
            float4 w0 = wr[0], w1 = wr[1], w2 = wr[2], w3 = wr[3];
            acc[0]  = fmaf(xv, w0.x, acc[0]);  acc[1]  = fmaf(xv, w0.y, acc[1]);
            acc[2]  = fmaf(xv, w0.z, acc[2]);  acc[3]  = fmaf(xv, w0.w, acc[3]);
            acc[4]  = fmaf(xv, w1.x, acc[4]);  acc[5]  = fmaf(xv, w1.y, acc[5]);
            acc[6]  = fmaf(xv, w1.z, acc[6]);  acc[7]  = fmaf(xv, w1.w, acc[7]);
            acc[8]  = fmaf(xv, w2.x, acc[8]);  acc[9]  = fmaf(xv, w2.y, acc[9]);
            acc[10] = fmaf(xv, w2.z, acc[10]); acc[11] = fmaf(xv, w2.w, acc[11]);
            acc[12] = fmaf(xv, w3.x, acc[12]); acc[13] = fmaf(xv, w3.y, acc[13]);
            acc[14] = fmaf(xv, w3.z, acc[14]); acc[15] = fmaf(xv, w3.w, acc[15]);
        }
    }
    if (n >= NN) return;
    float xp[HD], P[HD], Q[HD];
#pragma unroll
    for (int c = 0; c < HD; c++) {
        xp[c] = acc[c] + bs[c];
        float m = fmaxf(xp[c], 0.f) + MSG_EPS;
        P[c] = __expf(m);
        Q[c] = P[c] * m;
    }
    float4* xpo = (float4*)(g_xp + (size_t)n * HD);
    float4* pqo = (float4*)(g_PQ + (size_t)n * 32);
#pragma unroll
    for (int q = 0; q < 4; q++) {
        xpo[q] = make_float4(xp[q*4], xp[q*4+1], xp[q*4+2], xp[q*4+3]);
        pqo[q] = make_float4(P[q*4], P[q*4+1], P[q*4+2], P[q*4+3]);
        pqo[4+q] = make_float4(Q[q*4], Q[q*4+1], Q[q*4+2], Q[q*4+3]);
    }
}

// ---------------- aggregation + residual + W1: warp per node, paired edges ----------
// lanes 0-15 handle even edge, lanes 16-31 odd edge; each lane loads float2 (2 chans)
// 16-edge unrolled mainloop: 8 independent idx LDGs then 8 independent gathers (MLP~16)
__global__ void k_aggr(int conv, const float* __restrict__ W1, const float* __restrict__ b1) {
    __shared__ float w1s[HD * H2];
    __shared__ float b1s[H2];
    for (int i = threadIdx.x; i < HD * H2; i += blockDim.x) w1s[i] = W1[i];
    if (threadIdx.x < H2) b1s[threadIdx.x] = b1[threadIdx.x];
    __syncthreads();
    int n = (blockIdx.x * blockDim.x + threadIdx.x) >> 5;
    int lane = threadIdx.x & 31;
    if (n >= NN) return;
    int hw = lane >> 4;      // which edge of the pair
    int cl = lane & 15;      // float2 index within the 32-float row
    int s = g_ptr[n], e = g_ptr[n + 1];
    const float2* __restrict__ PQ2 = (const float2*)g_PQ;
    float ax = 0.f, ay = 0.f;
    int p = s;
    // 16 edges (8 pairs) per iteration: all idx loads independent, then all gathers
    for (; p + 16 <= e; p += 16) {
        int i0 = __ldg(g_csr + p      + hw);
        int i1 = __ldg(g_csr + p + 2  + hw);
        int i2 = __ldg(g_csr + p + 4  + hw);
        int i3 = __ldg(g_csr + p + 6  + hw);
        int i4 = __ldg(g_csr + p + 8  + hw);
        int i5 = __ldg(g_csr + p + 10 + hw);
        int i6 = __ldg(g_csr + p + 12 + hw);
        int i7 = __ldg(g_csr + p + 14 + hw);
        float2 v0 = __ldg(PQ2 + (size_t)i0 * 16 + cl);
        float2 v1 = __ldg(PQ2 + (size_t)i1 * 16 + cl);
        float2 v2 = __ldg(PQ2 + (size_t)i2 * 16 + cl);
        float2 v3 = __ldg(PQ2 + (size_t)i3 * 16 + cl);
        float2 v4 = __ldg(PQ2 + (size_t)i4 * 16 + cl);
        float2 v5 = __ldg(PQ2 + (size_t)i5 * 16 + cl);
        float2 v6 = __ldg(PQ2 + (size_t)i6 * 16 + cl);
        float2 v7 = __ldg(PQ2 + (size_t)i7 * 16 + cl);
        ax += ((v0.x + v1.x) + (v2.x + v3.x)) + ((v4.x + v5.x) + (v6.x + v7.x));
        ay += ((v0.y + v1.y) + (v2.y + v3.y)) + ((v4.y + v5.y) + (v6.y + v7.y));
    }
    // 8 edges (4 pairs)
    for (; p + 8 <= e; p += 8) {
        int i0 = __ldg(g_csr + p     + hw);
        int i1 = __ldg(g_csr + p + 2 + hw);
        int i2 = __ldg(g_csr + p + 4 + hw);
        int i3 = __ldg(g_csr + p + 6 + hw);
        float2 v0 = __ldg(PQ2 + (size_t)i0 * 16 + cl);
        float2 v1 = __ldg(PQ2 + (size_t)i1 * 16 + cl);
        float2 v2 = __ldg(PQ2 + (size_t)i2 * 16 + cl);
        float2 v3 = __ldg(PQ2 + (size_t)i3 * 16 + cl);
        ax += (v0.x + v1.x) + (v2.x + v3.x);
        ay += (v0.y + v1.y) + (v2.y + v3.y);
    }
    for (; p < e; p += 2) {
        int q = p + hw;
        int idx = __ldg(g_csr + (q < e ? q : p));
        float2 v = __ldg(PQ2 + (size_t)idx * 16 + cl);
        if (q < e) { ax += v.x; ay += v.y; }
    }
    // combine the two half-warps
    ax += __shfl_xor_sync(0xffffffffu, ax, 16);
    ay += __shfl_xor_sync(0xffffffffu, ay, 16);
    // lane c (0..15) wants P_c (lane c>>1) and Q_c (lane 8+(c>>1)); comp = c&1
    int c = lane;
    float px = __shfl_sync(0xffffffffu, ax, (c >> 1) & 15);
    float py = __shfl_sync(0xffffffffu, ay, (c >> 1) & 15);
    float qx = __shfl_sync(0xffffffffu, ax, 8 + ((c >> 1) & 15));
    float qy = __shfl_sync(0xffffffffu, ay, 8 + ((c >> 1) & 15));
    float Pv = (c & 1) ? py : px;
    float Qv = (c & 1) ? qy : qx;
    float h1 = 0.f;
    if (lane < HD) {
        float aggr = (e > s) ? (Qv / Pv) : 0.f;
        const float* resid = (conv == 1) ? g_xp : g_h;
        h1 = aggr + resid[(size_t)n * HD + lane];
    }
    float tv = b1s[lane];
#pragma unroll
    for (int cc = 0; cc < HD; cc++) {
        float hc = __shfl_sync(0xffffffffu, h1, cc);
        tv = fmaf(hc, w1s[cc * H2 + lane], tv);
    }
    g_t[(size_t)n * H2 + lane] = tv;
}

// ---------------- deterministic BN stats (partials) ----------------
__global__ void k_stats1() {
    __shared__ float sh[256];
    int b = blockIdx.x, tid = threadIdx.x;
    int c = tid & 31, rr = tid >> 5;
    float s = 0.f, q = 0.f;
    int r0 = b * RPB;
    int r1 = min(NN, (b + 1) * RPB);
    for (int r = r0 + rr; r < r1; r += 8) {
        float v = g_t[(size_t)r * H2 + c];
        s += v;
        q = fmaf(v, v, q);
    }
    sh[tid] = s;
    __syncthreads();
    if (tid < 32) {
        float t2 = 0.f;
#pragma unroll
        for (int k = 0; k < 8; k++) t2 += sh[tid + 32 * k];
        g_psum[b * 32 + tid] = t2;
    }
    __syncthreads();
    sh[tid] = q;
    __syncthreads();
    if (tid < 32) {
        float t2 = 0.f;
#pragma unroll
        for (int k = 0; k < 8; k++) t2 += sh[tid + 32 * k];
        g_psq[b * 32 + tid] = t2;
    }
}

// per-block redundant final stats reduction -> smem mu/rsig (scalar only, double accum)
__device__ __forceinline__ void stats_prologue(float* smu, float* srs, int tid) {
    if (tid < 32) {
        double s = 0.0, q = 0.0;
        for (int b = 0; b < SB; b++) {
            s += (double)g_psum[b * 32 + tid];
            q += (double)g_psq[b * 32 + tid];
        }
        double mu = s / (double)NN;
        double var = q / (double)NN - mu * mu;
        smu[tid] = (float)mu;
        srs[tid] = (float)rsqrt(var + (double)BN_EPS);
    }
    __syncthreads();
}

// ---------------- conv1 tail fused with conv2 pre: BN->relu->W2->relu => g_h, g_PQ ----
__global__ void k_post1(const float* __restrict__ gam, const float* __restrict__ bet,
                        const float* __restrict__ W2, const float* __restrict__ b2) {
    __shared__ float w2s[H2 * HD];
    __shared__ float sc[H2], sb[H2], smu[H2], srs[H2], b2s[HD];
    int tid = threadIdx.x;
    stats_prologue(smu, srs, tid);
    for (int i = tid; i < H2 * HD; i += blockDim.x) w2s[i] = W2[i];
    if (tid < H2) { sc[tid] = gam[tid]; sb[tid] = bet[tid]; }
    if (tid < HD) b2s[tid] = b2[tid];
    __syncthreads();
    int n = blockIdx.x * blockDim.x + tid;
    if (n >= NN) return;
    float r[H2];
    const float4* t4 = (const float4*)(g_t + (size_t)n * H2);
#pragma unroll
    for (int q = 0; q < H2 / 4; q++) {
        float4 v = t4[q];
        const float* f = (const float*)&v;
#pragma unroll
        for (int kk = 0; kk < 4; kk++) {
            int j = q * 4 + kk;
            float u = (f[kk] - smu[j]) * srs[j] * sc[j] + sb[j];
            r[j] = fmaxf(u, 0.f);
        }
    }
    float o[HD];
#pragma unroll
    for (int c = 0; c < HD; c++) o[c] = b2s[c];
#pragma unroll
    for (int j = 0; j < H2; j++) {
        float rj = r[j];
#pragma unroll
        for (int c = 0; c < HD; c++) o[c] = fmaf(rj, w2s[j * HD + c], o[c]);
    }
    float hv[HD], P[HD], Q[HD];
#pragma unroll
    for (int c = 0; c < HD; c++) {
        hv[c] = fmaxf(o[c], 0.f);
        float m = hv[c] + MSG_EPS;
        P[c] = __expf(m);
        Q[c] = P[c] * m;
    }
    float4* ho = (float4*)(g_h + (size_t)n * HD);
    float4* pqo = (float4*)(g_PQ + (size_t)n * 32);
#pragma unroll
    for (int q = 0; q < 4; q++) {
        ho[q] = make_float4(hv[q*4], hv[q*4+1], hv[q*4+2], hv[q*4+3]);
        pqo[q] = make_float4(P[q*4], P[q*4+1], P[q*4+2], P[q*4+3]);
        pqo[4+q] = make_float4(Q[q*4], Q[q*4+1], Q[q*4+2], Q[q*4+3]);
    }
}

// ---------------- conv2 tail + fc + masked compaction (direct write to out) ----------
__global__ void k_post2(const float* __restrict__ gam, const float* __restrict__ bet,
                        const float* __restrict__ W2, const float* __restrict__ b2,
                        const float* __restrict__ fcW, const float* __restrict__ fcb,
                        const int* __restrict__ mask, float* __restrict__ out) {
    __shared__ float w2s[H2 * HD];
    __shared__ float fws[HD * OUT_DIM];
    __shared__ float sc[H2], sb[H2], smu[H2], srs[H2], b2s[HD], fbs[OUT_DIM];
    int tid = threadIdx.x;
    stats_prologue(smu, srs, tid);
    for (int i = tid; i < H2 * HD; i += blockDim.x) w2s[i] = W2[i];
    for (int i = tid; i < HD * OUT_DIM; i += blockDim.x) fws[i] = fcW[i];
    if (tid < H2) { sc[tid] = gam[tid]; sb[tid] = bet[tid]; fbs[tid] = fcb[tid]; }
    if (tid < HD) b2s[tid] = b2[tid];
    __syncthreads();
    int n = blockIdx.x * blockDim.x + tid;
    if (n >= NN) return;
    float r[H2];
    const float4* t4 = (const float4*)(g_t + (size_t)n * H2);
#pragma unroll
    for (int q = 0; q < H2 / 4; q++) {
        float4 v = t4[q];
        const float* f = (const float*)&v;
#pragma unroll
        for (int kk = 0; kk < 4; kk++) {
            int j = q * 4 + kk;
            float u = (f[kk] - smu[j]) * srs[j] * sc[j] + sb[j];
            r[j] = fmaxf(u, 0.f);
        }
    }
    float hr[HD];
#pragma unroll
    for (int c = 0; c < HD; c++) hr[c] = b2s[c];
#pragma unroll
    for (int j = 0; j < H2; j++) {
        float rj = r[j];
#pragma unroll
        for (int c = 0; c < HD; c++) hr[c] = fmaf(rj, w2s[j * HD + c], hr[c]);
    }
#pragma unroll
    for (int c = 0; c < HD; c++) hr[c] = fmaxf(hr[c], 0.f);
    if (mask[n] == 0) return;
    float ov[OUT_DIM];
#pragma unroll
    for (int c2 = 0; c2 < OUT_DIM; c2++) ov[c2] = fbs[c2];
#pragma unroll
    for (int c = 0; c < HD; c++) {
        float hc = hr[c];
#pragma unroll
        for (int c2 = 0; c2 < OUT_DIM; c2++) ov[c2] = fmaf(hc, fws[c * OUT_DIM + c2], ov[c2]);
    }
    int pos = g_maskpos[n];
    float4* od = (float4*)(out + (size_t)pos * OUT_DIM);
#pragma unroll
    for (int q = 0; q < OUT_DIM / 4; q++)
        od[q] = make_float4(ov[q*4], ov[q*4+1], ov[q*4+2], ov[q*4+3]);
}

// ---------------- host ----------------
extern "C" void kernel_launch(void* const* d_in, const int* in_sizes, int n_in,
                              void* d_out, int out_size) {
    int base = (in_sizes[0] == 2 * EE) ? 0 : 1;
    const int*   edge_index = (const int*)d_in[base + 0];
    const float* x          = (const float*)d_in[base + 2];
    const int*   node_mask  = (const int*)d_in[base + 3];
    const float* W_src = (const float*)d_in[base + 4];
    const float* b_src = (const float*)d_in[base + 5];
    const float* c1_W1 = (const float*)d_in[base + 6];
    const float* c1_b1 = (const float*)d_in[base + 7];
    const float* c1_g  = (const float*)d_in[base + 8];
    const float* c1_be = (const float*)d_in[base + 9];
    const float* c1_W2 = (const float*)d_in[base + 10];
    const float* c1_b2 = (const float*)d_in[base + 11];
    const float* c2_W1 = (const float*)d_in[base + 12];
    const float* c2_b1 = (const float*)d_in[base + 13];
    const float* c2_g  = (const float*)d_in[base + 14];
    const float* c2_be = (const float*)d_in[base + 15];
    const float* c2_W2 = (const float*)d_in[base + 16];
    const float* c2_b2 = (const float*)d_in[base + 17];
    const float* fc_W  = (const float*)d_in[base + 18];
    const float* fc_b  = (const float*)d_in[base + 19];
    float* out = (float*)d_out;

    const int TPB = 256;
    const int EB = (EE + TPB - 1) / TPB;       // 12500
    const int NB = (NN + TPB - 1) / TPB;       // 391
    const int WB = (NN * 32 + TPB - 1) / TPB;  // 12500 (warp-per-node)

    // CSR build + mask positions
    k_zero_detect<<<NB, TPB>>>((const unsigned int*)edge_index);
    k_hist<<<EB, TPB>>>(edge_index);
    kScanA<<<NSCAN, 1024>>>(node_mask);
    kScanB<<<1, 128>>>();
    kScanC<<<NSCAN, 1024>>>(node_mask);
    k_scatter<<<EB, TPB>>>(edge_index);

    // conv1
    k_pre1<<<NB, TPB>>>(x, W_src, b_src);
    k_aggr<<<WB, TPB>>>(1, c1_W1, c1_b1);
    k_stats1<<<SB, 256>>>();
    k_post1<<<NB, TPB>>>(c1_g, c1_be, c1_W2, c1_b2);

    // conv2 + fc + masked write
    k_aggr<<<WB, TPB>>>(2, c2_W1, c2_b1);
    k_stats1<<<SB, 256>>>();
    k_post2<<<NB, TPB>>>(c2_g, c2_be, c2_W2, c2_b2, fc_W, fc_b, node_mask, out);
}